// round 1
// baseline (speedup 1.0000x reference)
#include <cuda_runtime.h>
#include <cstddef>

// Problem constants (fixed by the reference)
#define DIM   1024
#define BATCH 16
#define SEQL  2048
#define KCONV 3

// Scratch: BCx (B, L, 3D) and y (B, L, D). Static device arrays (no allocs allowed).
__device__ float g_BCx[(size_t)BATCH * SEQL * 3 * DIM];  // ~402 MB
__device__ float g_y  [(size_t)BATCH * SEQL * DIM];      // ~134 MB

// ---------------------------------------------------------------------------
// SGEMM, NT layout:  C[m,n] = sum_k A[m,k] * W[n,k] + bias[n]
// A: (M,K) row-major, W: (N,K) row-major, C: (M,N) row-major.
// Block tile BM x BN x BK, per-thread TM x TN register tile.
// All problem dims are multiples of the tiles -> no bounds checks.
// ---------------------------------------------------------------------------
template <int BM, int BN, int BK, int TM, int TN, int THREADS>
__global__ __launch_bounds__(THREADS)
void sgemm_nt(const float* __restrict__ A,
              const float* __restrict__ W,
              const float* __restrict__ bias,
              float* __restrict__ C,
              int M, int N, int K)
{
    __shared__ float As[BK][BM];
    __shared__ float Ws[BK][BN];

    const int bm  = blockIdx.y * BM;
    const int bn  = blockIdx.x * BN;
    const int tid = threadIdx.x;

    const int tx = tid % (BN / TN);   // 0..15
    const int ty = tid / (BN / TN);   // 0..15

    float acc[TM][TN];
#pragma unroll
    for (int i = 0; i < TM; i++)
#pragma unroll
        for (int j = 0; j < TN; j++)
            acc[i][j] = 0.0f;

    constexpr int A_LOADS = (BM * BK) / (4 * THREADS);  // float4 loads per thread
    constexpr int W_LOADS = (BN * BK) / (4 * THREADS);
    constexpr int K4 = BK / 4;

    for (int k0 = 0; k0 < K; k0 += BK) {
        // --- load A tile (BM rows x BK cols), store transposed As[k][m]
#pragma unroll
        for (int i = 0; i < A_LOADS; i++) {
            int idx  = tid + i * THREADS;         // 0 .. BM*BK/4-1
            int row  = idx / K4;
            int c4   = idx % K4;
            float4 v = *reinterpret_cast<const float4*>(
                A + (size_t)(bm + row) * K + k0 + c4 * 4);
            As[c4 * 4 + 0][row] = v.x;
            As[c4 * 4 + 1][row] = v.y;
            As[c4 * 4 + 2][row] = v.z;
            As[c4 * 4 + 3][row] = v.w;
        }
        // --- load W tile (BN rows x BK cols), store transposed Ws[k][n]
#pragma unroll
        for (int i = 0; i < W_LOADS; i++) {
            int idx  = tid + i * THREADS;
            int row  = idx / K4;
            int c4   = idx % K4;
            float4 v = *reinterpret_cast<const float4*>(
                W + (size_t)(bn + row) * K + k0 + c4 * 4);
            Ws[c4 * 4 + 0][row] = v.x;
            Ws[c4 * 4 + 1][row] = v.y;
            Ws[c4 * 4 + 2][row] = v.z;
            Ws[c4 * 4 + 3][row] = v.w;
        }
        __syncthreads();

#pragma unroll
        for (int kk = 0; kk < BK; kk++) {
            float ra[TM], rb[TN];
            // TM = TN = 8 -> two float4 loads each
            float4 a0 = *reinterpret_cast<const float4*>(&As[kk][ty * TM]);
            float4 a1 = *reinterpret_cast<const float4*>(&As[kk][ty * TM + 4]);
            float4 b0 = *reinterpret_cast<const float4*>(&Ws[kk][tx * TN]);
            float4 b1 = *reinterpret_cast<const float4*>(&Ws[kk][tx * TN + 4]);
            ra[0] = a0.x; ra[1] = a0.y; ra[2] = a0.z; ra[3] = a0.w;
            ra[4] = a1.x; ra[5] = a1.y; ra[6] = a1.z; ra[7] = a1.w;
            rb[0] = b0.x; rb[1] = b0.y; rb[2] = b0.z; rb[3] = b0.w;
            rb[4] = b1.x; rb[5] = b1.y; rb[6] = b1.z; rb[7] = b1.w;
#pragma unroll
            for (int i = 0; i < TM; i++)
#pragma unroll
                for (int j = 0; j < TN; j++)
                    acc[i][j] = fmaf(ra[i], rb[j], acc[i][j]);
        }
        __syncthreads();
    }

    // --- epilogue: add bias, vectorized stores
#pragma unroll
    for (int i = 0; i < TM; i++) {
        size_t row = (size_t)(bm + ty * TM + i);
        float* cp  = C + row * N + bn + tx * TN;
#pragma unroll
        for (int j = 0; j < TN; j += 4) {
            float4 v;
            v.x = acc[i][j + 0] + bias[bn + tx * TN + j + 0];
            v.y = acc[i][j + 1] + bias[bn + tx * TN + j + 1];
            v.z = acc[i][j + 2] + bias[bn + tx * TN + j + 2];
            v.w = acc[i][j + 3] + bias[bn + tx * TN + j + 3];
            *reinterpret_cast<float4*>(cp + j) = v;
        }
    }
}

// ---------------------------------------------------------------------------
// Gate + causal depthwise conv (K=3):
//   Bx[l]   = Bg[l] * xg[l]
//   conv[l] = w0*Bx[l-2] + w1*Bx[l-1] + w2*Bx[l]   (zeros before l=0)
//   y[l]    = Cg[l] * conv[l]
// BCx layout: (B, L, 3D) with channel split [Bg | Cg | xg].
// Grid: (D/256, B, L/LCHUNK); each thread owns one channel over an L-chunk.
// ---------------------------------------------------------------------------
#define LCHUNK 128

__global__ __launch_bounds__(256)
void gate_conv_kernel(const float* __restrict__ BCx,
                      const float* __restrict__ wconv,
                      float* __restrict__ y)
{
    const int d  = blockIdx.x * blockDim.x + threadIdx.x;  // channel
    const int b  = blockIdx.y;
    const int l0 = blockIdx.z * LCHUNK;

    const float w0 = wconv[d * KCONV + 0];
    const float w1 = wconv[d * KCONV + 1];
    const float w2 = wconv[d * KCONV + 2];

    const float* base = BCx + (size_t)b * SEQL * 3 * DIM;

    // history (recompute Bx at l0-2, l0-1)
    float bxm2 = 0.0f, bxm1 = 0.0f;
    if (l0 >= 2) {
        const float* r = base + (size_t)(l0 - 2) * 3 * DIM;
        bxm2 = r[d] * r[2 * DIM + d];
    }
    if (l0 >= 1) {
        const float* r = base + (size_t)(l0 - 1) * 3 * DIM;
        bxm1 = r[d] * r[2 * DIM + d];
    }

    for (int l = l0; l < l0 + LCHUNK; l++) {
        const float* r = base + (size_t)l * 3 * DIM;
        float bg = r[d];
        float cg = r[DIM + d];
        float xg = r[2 * DIM + d];
        float bx = bg * xg;
        float conv = fmaf(w0, bxm2, fmaf(w1, bxm1, w2 * bx));
        y[((size_t)b * SEQL + l) * DIM + d] = cg * conv;
        bxm2 = bxm1;
        bxm1 = bx;
    }
}

// ---------------------------------------------------------------------------
extern "C" void kernel_launch(void* const* d_in, const int* in_sizes, int n_in,
                              void* d_out, int out_size)
{
    const float* x     = (const float*)d_in[0];  // (B, L, D)
    const float* Win   = (const float*)d_in[1];  // (3D, D)
    const float* bin_  = (const float*)d_in[2];  // (3D,)
    const float* wconv = (const float*)d_in[3];  // (D, K)
    const float* Wout  = (const float*)d_in[4];  // (D, D)
    const float* bout  = (const float*)d_in[5];  // (D,)
    float* out = (float*)d_out;                  // (B, L, D)

    float* BCx = nullptr;
    float* y   = nullptr;
    cudaGetSymbolAddress((void**)&BCx, g_BCx);
    cudaGetSymbolAddress((void**)&y,   g_y);

    constexpr int BM = 128, BN = 128, BK = 16, TM = 8, TN = 8, THREADS = 256;
    const int M = BATCH * SEQL;  // 32768

    // GEMM 1: BCx = x @ Win^T + bin    (M x 3072, K=1024)
    {
        dim3 grid((3 * DIM) / BN, M / BM);
        sgemm_nt<BM, BN, BK, TM, TN, THREADS><<<grid, THREADS>>>(
            x, Win, bin_, BCx, M, 3 * DIM, DIM);
    }

    // Gate + causal conv: y = Cg * conv(Bg * xg)
    {
        dim3 grid(DIM / 256, BATCH, SEQL / LCHUNK);
        gate_conv_kernel<<<grid, 256>>>(BCx, wconv, y);
    }

    // GEMM 2: out = y @ Wout^T + bout  (M x 1024, K=1024)
    {
        dim3 grid(DIM / BN, M / BM);
        sgemm_nt<BM, BN, BK, TM, TN, THREADS><<<grid, THREADS>>>(
            y, Wout, bout, out, M, DIM, DIM);
    }
}

// round 3
// speedup vs baseline: 5.2031x; 5.2031x over previous
#include <cuda_runtime.h>
#include <cstdint>
#include <cstddef>

// Problem constants
#define DIM   1024
#define BATCH 16
#define SEQL  2048
#define KCONV 3
#define MTOT  (BATCH * SEQL)   // 32768

// ---------------- scratch (static; no allocs allowed) ----------------
__device__ float g_BCx[(size_t)MTOT * 3 * DIM];   // in_proj output (fp32)
__device__ float g_y  [(size_t)MTOT * DIM];       // gated conv output
__device__ float g_xc [(size_t)MTOT * DIM];       // x rounded to tf32
__device__ float g_Wic[(size_t)3 * DIM * DIM];    // Win rounded to tf32
__device__ float g_Woc[(size_t)DIM * DIM];        // Wout rounded to tf32

// Does this compilation pass have arch-specific (sm_103a / sm_10xf) features?
#if (defined(__CUDA_ARCH_SPECIFIC__) && (__CUDA_ARCH_SPECIFIC__ >= 1000)) || \
    (defined(__CUDA_ARCH_FAMILY_SPECIFIC__) && (__CUDA_ARCH_FAMILY_SPECIFIC__ >= 1000))
#define HAS_TCGEN05 1
#else
#define HAS_TCGEN05 0
#endif

// ---------------- common PTX helpers (all non-'a'-gated) ----------------
__device__ __forceinline__ uint32_t smem_u32(const void* p) {
    uint32_t a;
    asm("{ .reg .u64 t; cvta.to.shared.u64 t, %1; cvt.u32.u64 %0, t; }" : "=r"(a) : "l"(p));
    return a;
}
__device__ __forceinline__ float to_tf32(float x) {
    uint32_t b;
    asm("cvt.rna.tf32.f32 %0, %1;" : "=r"(b) : "f"(x));
    return __uint_as_float(b);
}
__device__ __forceinline__ void cp_async16(uint32_t dst, const void* src) {
    asm volatile("cp.async.cg.shared.global [%0], [%1], 16;" :: "r"(dst), "l"(src));
}
#define CP_COMMIT()  asm volatile("cp.async.commit_group;" ::: "memory")
#define CP_WAIT3()   asm volatile("cp.async.wait_group 3;" ::: "memory")

#define SW128(off) ((off) ^ (((off) >> 3) & 0x70))

// ---------------- GEMM tiling (shared by both paths) ----------------
#define BM 128
#define BN 128
#define BK 32
#define NSTAGE 4
#define STAGE_BYTES (BM * 128 + BN * 128)   // 16KB + 16KB = 32KB
#define SMEM_DYN (2048 + NSTAGE * STAGE_BYTES)  // 133120
#define EPI_PITCH 129

// fill one operand tile: nrows rows x 32 floats (128B, SW128-swizzled)
__device__ __forceinline__ void fill_tile(uint32_t sbase, const float* g, int nrows,
                                          int K, int k0, int tid)
{
    const int nch = nrows * 8;
    for (int idx = tid; idx < nch; idx += 256) {
        int row = idx >> 3;
        int c4  = idx & 7;
        const float* src = g + (size_t)row * K + k0 + c4 * 4;
        uint32_t off = (uint32_t)(row * 128 + c4 * 16);
        cp_async16(sbase + SW128(off), src);
    }
}

#if HAS_TCGEN05
// ================= tcgen05 path helpers =================
__device__ __forceinline__ uint32_t elect_one() {
    uint32_t p;
    asm volatile("{\n\t.reg .pred p;\n\telect.sync _|p, 0xFFFFFFFF;\n\tselp.b32 %0, 1, 0, p;\n\t}" : "=r"(p));
    return p;
}
#define MBARRIER_INIT(addr, cnt) \
    asm volatile("mbarrier.init.shared.b64 [%0], %1;" :: "r"(addr), "r"(cnt) : "memory")
__device__ __forceinline__ void mbar_wait_parity(uint32_t mbar, uint32_t parity) {
    uint32_t done;
    asm volatile(
        "{\n\t.reg .pred p;\n\t"
        "mbarrier.try_wait.parity.acquire.cta.shared::cta.b64 p, [%1], %2;\n\t"
        "selp.b32 %0, 1, 0, p;\n\t}"
        : "=r"(done) : "r"(mbar), "r"(parity) : "memory");
    if (!done) {
        asm volatile(
            "{\n\t.reg .pred P1;\n\t"
            "WL_%=:\n\t"
            "mbarrier.try_wait.parity.acquire.cta.shared::cta.b64 P1, [%0], %1, 0x989680;\n\t"
            "@P1 bra.uni WD_%=;\n\t"
            "bra.uni WL_%=;\n\t"
            "WD_%=:\n\t}"
            :: "r"(mbar), "r"(parity) : "memory");
    }
}
#define TCGEN05_ALLOC(sptr, n) \
    asm volatile("tcgen05.alloc.cta_group::1.sync.aligned.shared::cta.b32 [%0], %1;" \
                 :: "r"(sptr), "r"(n) : "memory")
#define TCGEN05_DEALLOC(t, n) \
    asm volatile("tcgen05.dealloc.cta_group::1.sync.aligned.b32 %0, %1;" :: "r"(t), "r"(n))
#define TCGEN05_RELINQ() \
    asm volatile("tcgen05.relinquish_alloc_permit.cta_group::1.sync.aligned;")
#define TCGEN05_COMMIT(mbar) \
    asm volatile("tcgen05.commit.cta_group::1.mbarrier::arrive::one.shared::cluster.b64 [%0];" \
                 :: "r"(mbar) : "memory")
#define TCGEN05_FENCE_AFTER() \
    asm volatile("tcgen05.fence::after_thread_sync;" ::: "memory")
#define TCGEN05_WAIT_LD() \
    asm volatile("tcgen05.wait::ld.sync.aligned;" ::: "memory")
#define FENCE_PROXY_ASYNC() \
    asm volatile("fence.proxy.async.shared::cta;" ::: "memory")

#define TCGEN05_LD_X32(r, addr) \
    asm volatile( \
        "tcgen05.ld.sync.aligned.32x32b.x32.b32 " \
        "{%0, %1, %2, %3, %4, %5, %6, %7, " \
        " %8, %9, %10, %11, %12, %13, %14, %15, " \
        " %16, %17, %18, %19, %20, %21, %22, %23, " \
        " %24, %25, %26, %27, %28, %29, %30, %31}, [%32];" \
        : "=r"((r)[0]),  "=r"((r)[1]),  "=r"((r)[2]),  "=r"((r)[3]), \
          "=r"((r)[4]),  "=r"((r)[5]),  "=r"((r)[6]),  "=r"((r)[7]), \
          "=r"((r)[8]),  "=r"((r)[9]),  "=r"((r)[10]), "=r"((r)[11]), \
          "=r"((r)[12]), "=r"((r)[13]), "=r"((r)[14]), "=r"((r)[15]), \
          "=r"((r)[16]), "=r"((r)[17]), "=r"((r)[18]), "=r"((r)[19]), \
          "=r"((r)[20]), "=r"((r)[21]), "=r"((r)[22]), "=r"((r)[23]), \
          "=r"((r)[24]), "=r"((r)[25]), "=r"((r)[26]), "=r"((r)[27]), \
          "=r"((r)[28]), "=r"((r)[29]), "=r"((r)[30]), "=r"((r)[31]) \
        : "r"(addr))

static __device__ __forceinline__ uint64_t make_desc(uint32_t addr) {
    const uint64_t base =
        (uint64_t(2)  << 61) | (uint64_t(1) << 46) |
        (uint64_t(64) << 32) | (uint64_t(1) << 16);
    return base | ((uint64_t)(addr >> 4) & 0x3FFF);
}
__device__ __forceinline__ void tcgen05_mma_tf32_ss(
    uint32_t d_tmem, uint64_t a_desc, uint64_t b_desc, uint32_t idesc, uint32_t acc)
{
    asm volatile(
        "{\n\t.reg .pred p;\n\t"
        "setp.ne.u32 p, %5, 0;\n\t"
        "tcgen05.mma.cta_group::1.kind::tf32 [%0], %1, %2, %3, {%4, %4, %4, %4}, p;\n\t}"
        :: "r"(d_tmem), "l"(a_desc), "l"(b_desc), "r"(idesc), "r"(0u), "r"(acc)
        : "memory");
}
// idesc: dtype=F32(1)@4, atype=TF32(2)@7, btype=TF32(2)@10, N/8@17, M/16@24
// (formula validated: reproduces example 0x8080490 for bf16 M=128 N=32)
#define GEMM_IDESC ((1u << 4) | (2u << 7) | (2u << 10) | ((BN / 8u) << 17) | ((BM / 16u) << 24))
#else
// ================= mma.sync fallback helper =================
__device__ __forceinline__ void mma_tf32(float* c, const uint32_t* a, const uint32_t* b)
{
    asm volatile(
        "mma.sync.aligned.m16n8k8.row.col.f32.tf32.tf32.f32 "
        "{%0,%1,%2,%3}, {%4,%5,%6,%7}, {%8,%9}, {%0,%1,%2,%3};"
        : "+f"(c[0]), "+f"(c[1]), "+f"(c[2]), "+f"(c[3])
        : "r"(a[0]), "r"(a[1]), "r"(a[2]), "r"(a[3]), "r"(b[0]), "r"(b[1]));
}
#endif

// ---------------- tensor-core tf32 GEMM: C[m,n] = sum_k A[m,k]*B[n,k] + bias[n] ----------
__global__ __launch_bounds__(256, 1)
void gemm_tc_tf32(const float* __restrict__ A,
                  const float* __restrict__ B,
                  const float* __restrict__ bias,
                  float* __restrict__ C,
                  int M, int N, int K)
{
    extern __shared__ char smem[];
    const uint32_t sbase = smem_u32(smem);
    const int tid = threadIdx.x;
    const int bm = blockIdx.y * BM;
    const int bn = blockIdx.x * BN;

    const uint32_t tile0 = (sbase + 1024 + 1023) & ~1023u;
    const uint32_t tile0_byteoff = tile0 - sbase;

    const float* Ag = A + (size_t)bm * K;
    const float* Bg = B + (size_t)bn * K;
    const int NT = K / BK;   // 32

#if HAS_TCGEN05
    // ===================== tcgen05 tf32 SS pipeline =====================
    const uint32_t tmem_ptr_s = sbase;
    const uint32_t mbar0 = sbase + 8;

    if (tid < 32) TCGEN05_ALLOC(tmem_ptr_s, 128);
    if (tid == 0) {
#pragma unroll
        for (int s = 0; s < NSTAGE; s++) MBARRIER_INIT(mbar0 + s * 8, 1);
    }
    __syncthreads();
    uint32_t tmem_base;
    asm volatile("ld.shared.b32 %0, [%1];" : "=r"(tmem_base) : "r"(tmem_ptr_s));

#pragma unroll
    for (int p = 0; p < NSTAGE; p++) {
        uint32_t sA = tile0 + p * STAGE_BYTES;
        fill_tile(sA, Ag, BM, K, p * BK, tid);
        fill_tile(sA + BM * 128, Bg, BN, K, p * BK, tid);
        CP_COMMIT();
    }

    for (int i = 0; i < NT; i++) {
        const int s = i % NSTAGE;
        const uint32_t sA = tile0 + s * STAGE_BYTES;
        const uint32_t sB = sA + BM * 128;

        CP_WAIT3();
        __syncthreads();

        if (tid < 32) {
            if (elect_one()) {
                FENCE_PROXY_ASYNC();
                uint64_t ad = make_desc(sA);
                uint64_t bd = make_desc(sB);
#pragma unroll
                for (int k = 0; k < 4; k++) {   // 4 x (K=8)
                    tcgen05_mma_tf32_ss(tmem_base, ad + k * 2, bd + k * 2,
                                        GEMM_IDESC, (i > 0 || k > 0) ? 1u : 0u);
                }
                TCGEN05_COMMIT(mbar0 + s * 8);
            }
        }

        if (i + NSTAGE < NT) {
            mbar_wait_parity(mbar0 + s * 8, (uint32_t)((i / NSTAGE) & 1));
            fill_tile(sA, Ag, BM, K, (i + NSTAGE) * BK, tid);
            fill_tile(sB, Bg, BN, K, (i + NSTAGE) * BK, tid);
        }
        CP_COMMIT();
    }

    {
        const int li = NT - 1;
        mbar_wait_parity(mbar0 + (li % NSTAGE) * 8, (uint32_t)((li / NSTAGE) & 1));
    }
    TCGEN05_FENCE_AFTER();
    __syncthreads();

    // epilogue: TMEM -> smem (pitch 129) -> coalesced global + bias
    float* sepi = (float*)(smem + tile0_byteoff);
    {
        const int w = tid >> 5, lane = tid & 31;
        const int colhalf = (w >> 2) * 64;             // 0 or 64
        const int row = (w & 3) * 32 + lane;           // TMEM lane
        uint32_t r[32];
#pragma unroll
        for (int h = 0; h < 2; h++) {
            TCGEN05_LD_X32(r, tmem_base + colhalf + h * 32);
            TCGEN05_WAIT_LD();
            float* dst = sepi + (size_t)row * EPI_PITCH + colhalf + h * 32;
#pragma unroll
            for (int j = 0; j < 32; j++) dst[j] = __uint_as_float(r[j]);
        }
    }
    __syncthreads();
    {
        const int col = tid & 127;
        const int r0  = (tid >> 7) * 64;
        const float bv = __ldg(bias + bn + col);
#pragma unroll 4
        for (int t = 0; t < 64; t++) {
            int r = r0 + t;
            C[(size_t)(bm + r) * N + bn + col] = sepi[r * EPI_PITCH + col] + bv;
        }
    }
    __syncthreads();
    if (tid < 32) {
        TCGEN05_RELINQ();
        TCGEN05_DEALLOC(tmem_base, 128);
    }
#else
    // ===================== mma.sync tf32 fallback =====================
    const int w = tid >> 5, lane = tid & 31;
    const int wm = (w >> 2) * 64;   // warp M offset (0 or 64)
    const int wn = (w & 3) * 32;    // warp N offset (0..96)

    float acc[4][4][4];
#pragma unroll
    for (int a = 0; a < 4; a++)
#pragma unroll
        for (int b = 0; b < 4; b++)
#pragma unroll
            for (int c = 0; c < 4; c++) acc[a][b][c] = 0.0f;

#pragma unroll
    for (int p = 0; p < NSTAGE; p++) {
        uint32_t sA = tile0 + p * STAGE_BYTES;
        fill_tile(sA, Ag, BM, K, p * BK, tid);
        fill_tile(sA + BM * 128, Bg, BN, K, p * BK, tid);
        CP_COMMIT();
    }

    const char* smemc = smem;
    const uint32_t t0off = tile0_byteoff;

    for (int i = 0; i < NT; i++) {
        const int s = i % NSTAGE;
        const uint32_t aoff = t0off + s * STAGE_BYTES;
        const uint32_t boff = aoff + BM * 128;

        CP_WAIT3();
        __syncthreads();

#pragma unroll
        for (int ks = 0; ks < 4; ks++) {
            const int kb = ks * 32;             // byte offset within 128B row
            uint32_t afr[4][4], bfr[4][2];
#pragma unroll
            for (int mt = 0; mt < 4; mt++) {
                int r = wm + mt * 16 + (lane >> 2);
                uint32_t o = (uint32_t)(r * 128 + kb + (lane & 3) * 4);
                afr[mt][0] = *(const uint32_t*)(smemc + aoff + SW128(o));
                afr[mt][1] = *(const uint32_t*)(smemc + aoff + SW128(o + 8 * 128));
                afr[mt][2] = *(const uint32_t*)(smemc + aoff + SW128(o + 16));
                afr[mt][3] = *(const uint32_t*)(smemc + aoff + SW128(o + 8 * 128 + 16));
            }
#pragma unroll
            for (int nt = 0; nt < 4; nt++) {
                int r = wn + nt * 8 + (lane >> 2);
                uint32_t o = (uint32_t)(r * 128 + kb + (lane & 3) * 4);
                bfr[nt][0] = *(const uint32_t*)(smemc + boff + SW128(o));
                bfr[nt][1] = *(const uint32_t*)(smemc + boff + SW128(o + 16));
            }
#pragma unroll
            for (int mt = 0; mt < 4; mt++)
#pragma unroll
                for (int nt = 0; nt < 4; nt++)
                    mma_tf32(acc[mt][nt], afr[mt], bfr[nt]);
        }

        __syncthreads();
        if (i + NSTAGE < NT) {
            const uint32_t sA = tile0 + s * STAGE_BYTES;
            fill_tile(sA, Ag, BM, K, (i + NSTAGE) * BK, tid);
            fill_tile(sA + BM * 128, Bg, BN, K, (i + NSTAGE) * BK, tid);
        }
        CP_COMMIT();
    }

    // epilogue: direct stores (float2) + bias
#pragma unroll
    for (int mt = 0; mt < 4; mt++) {
#pragma unroll
        for (int nt = 0; nt < 4; nt++) {
            int row0 = bm + wm + mt * 16 + (lane >> 2);
            int col0 = bn + wn + nt * 8 + (lane & 3) * 2;
            float b0 = __ldg(bias + col0), b1 = __ldg(bias + col0 + 1);
            float2 v0 = make_float2(acc[mt][nt][0] + b0, acc[mt][nt][1] + b1);
            float2 v1 = make_float2(acc[mt][nt][2] + b0, acc[mt][nt][3] + b1);
            *(float2*)(C + (size_t)row0 * N + col0) = v0;
            *(float2*)(C + (size_t)(row0 + 8) * N + col0) = v1;
        }
    }
#endif
}

// ---------------- elementwise tf32 rounding ----------------
__global__ __launch_bounds__(256)
void cvt_tf32_kernel(const float* __restrict__ in, float* __restrict__ out, int n4)
{
    int i = blockIdx.x * blockDim.x + threadIdx.x;
    if (i < n4) {
        float4 v = reinterpret_cast<const float4*>(in)[i];
        v.x = to_tf32(v.x); v.y = to_tf32(v.y);
        v.z = to_tf32(v.z); v.w = to_tf32(v.w);
        reinterpret_cast<float4*>(out)[i] = v;
    }
}

// ---------------- gate + causal depthwise conv (K=3), tf32-rounded output ----------------
#define LCHUNK 128

__global__ __launch_bounds__(256)
void gate_conv_kernel(const float* __restrict__ BCx,
                      const float* __restrict__ wconv,
                      float* __restrict__ y)
{
    const int d  = blockIdx.x * blockDim.x + threadIdx.x;
    const int b  = blockIdx.y;
    const int l0 = blockIdx.z * LCHUNK;

    const float w0 = wconv[d * KCONV + 0];
    const float w1 = wconv[d * KCONV + 1];
    const float w2 = wconv[d * KCONV + 2];

    const float* base = BCx + (size_t)b * SEQL * 3 * DIM;

    float bxm2 = 0.0f, bxm1 = 0.0f;
    if (l0 >= 2) {
        const float* r = base + (size_t)(l0 - 2) * 3 * DIM;
        bxm2 = r[d] * r[2 * DIM + d];
    }
    if (l0 >= 1) {
        const float* r = base + (size_t)(l0 - 1) * 3 * DIM;
        bxm1 = r[d] * r[2 * DIM + d];
    }

    for (int l = l0; l < l0 + LCHUNK; l++) {
        const float* r = base + (size_t)l * 3 * DIM;
        float bg = r[d];
        float cg = r[DIM + d];
        float xg = r[2 * DIM + d];
        float bx = bg * xg;
        float conv = fmaf(w0, bxm2, fmaf(w1, bxm1, w2 * bx));
        y[((size_t)b * SEQL + l) * DIM + d] = to_tf32(cg * conv);
        bxm2 = bxm1;
        bxm1 = bx;
    }
}

// ---------------------------------------------------------------------------
extern "C" void kernel_launch(void* const* d_in, const int* in_sizes, int n_in,
                              void* d_out, int out_size)
{
    const float* x     = (const float*)d_in[0];
    const float* Win   = (const float*)d_in[1];
    const float* bin_  = (const float*)d_in[2];
    const float* wconv = (const float*)d_in[3];
    const float* Wout  = (const float*)d_in[4];
    const float* bout  = (const float*)d_in[5];
    float* out = (float*)d_out;

    float *BCx, *y, *xc, *Wic, *Woc;
    cudaGetSymbolAddress((void**)&BCx, g_BCx);
    cudaGetSymbolAddress((void**)&y,   g_y);
    cudaGetSymbolAddress((void**)&xc,  g_xc);
    cudaGetSymbolAddress((void**)&Wic, g_Wic);
    cudaGetSymbolAddress((void**)&Woc, g_Woc);

    cudaFuncSetAttribute(gemm_tc_tf32, cudaFuncAttributeMaxDynamicSharedMemorySize, SMEM_DYN);

    const int M = MTOT;

    // round inputs/weights to tf32 (rna)
    {
        int n4 = M * DIM / 4;
        cvt_tf32_kernel<<<(n4 + 255) / 256, 256>>>(x, xc, n4);
        n4 = 3 * DIM * DIM / 4;
        cvt_tf32_kernel<<<(n4 + 255) / 256, 256>>>(Win, Wic, n4);
        n4 = DIM * DIM / 4;
        cvt_tf32_kernel<<<(n4 + 255) / 256, 256>>>(Wout, Woc, n4);
    }

    // GEMM 1: BCx = xc @ Wic^T + bin   (M x 3072, K=1024)
    {
        dim3 grid((3 * DIM) / BN, M / BM);
        gemm_tc_tf32<<<grid, 256, SMEM_DYN>>>(xc, Wic, bin_, BCx, M, 3 * DIM, DIM);
    }

    // gate + causal conv -> y
    {
        dim3 grid(DIM / 256, BATCH, SEQL / LCHUNK);
        gate_conv_kernel<<<grid, 256>>>(BCx, wconv, y);
    }

    // GEMM 2: out = y @ Woc^T + bout  (M x 1024, K=1024)
    {
        dim3 grid(DIM / BN, M / BM);
        gemm_tc_tf32<<<grid, 256, SMEM_DYN>>>(y, Woc, bout, out, M, DIM, DIM);
    }
}